// round 5
// baseline (speedup 1.0000x reference)
#include <cuda_runtime.h>
#include <math.h>

#define NBATCH  16
#define NATOM   512
#define NEIGH   64
#define NPAIR   (NATOM*NEIGH)        /* 32768  */
#define TOTATOM (NBATCH*NATOM)       /* 8192   */
#define NPTOT   (NBATCH*NPAIR)       /* 524288 */
#define NWAVE   8
#define NL      13
#define NFEAT   104                  /* NL * NWAVE */
#define NORBIT  128
#define CAP     192                  /* bucket capacity per atom (mean 64) */
#define GATOMS  16

// Scratch: per-atom pair buckets, 16B records: (dx, dy, dz, species_j bits)
__device__ float4 d_rec[(size_t)TOTATOM * CAP];
__device__ int    d_cursor[TOTATOM];           // zero-init; self-cleaned by k_accum
__device__ float  d_sw[(size_t)TOTATOM * NFEAT];

// ---------------------------------------------------------------------------
// Kernel 1: displacement vector + species, bucketed. 4 pairs/thread for MLP.
// ---------------------------------------------------------------------------
__global__ void __launch_bounds__(256)
k_pairs(const float* __restrict__ cart,
        const int*   __restrict__ species,
        const int*   __restrict__ atom_index,
        const float* __restrict__ shifts)
{
    __shared__ float scart[NATOM * 3];
    __shared__ int   ssp  [NATOM];

    const int b   = blockIdx.y;
    const int tid = threadIdx.x;

    const float* cb = cart + (size_t)b * NATOM * 3;
    for (int i = tid; i < NATOM * 3; i += 256) scart[i] = cb[i];
    for (int i = tid; i < NATOM;     i += 256) ssp[i]   = species[b * NATOM + i];
    __syncthreads();

    int    ig [4];
    float4 rec[4];
#pragma unroll
    for (int u = 0; u < 4; ++u) {
        const int p_loc = blockIdx.x * 1024 + u * 256 + tid;
        const int p     = b * NPAIR + p_loc;

        const int i_loc = atom_index[p];
        const int j_loc = atom_index[NPTOT + p];

        float dx = scart[3*i_loc+0] - scart[3*j_loc+0] + shifts[3*p+0];
        float dy = scart[3*i_loc+1] - scart[3*j_loc+1] + shifts[3*p+1];
        float dz = scart[3*i_loc+2] - scart[3*j_loc+2] + shifts[3*p+2];

        rec[u] = make_float4(dx, dy, dz, __int_as_float(ssp[j_loc]));
        ig[u]  = b * NATOM + i_loc;
    }

    int pos[4];
#pragma unroll
    for (int u = 0; u < 4; ++u)               // independent atomics: MLP=4
        pos[u] = atomicAdd(&d_cursor[ig[u]], 1);
#pragma unroll
    for (int u = 0; u < 4; ++u)
        if (pos[u] < CAP)
            d_rec[(size_t)ig[u] * CAP + pos[u]] = rec[u];
}

// ---------------------------------------------------------------------------
// Kernel 2a: block per atom -> sw[13][8].
// Phase A: per-pair (d, fc). Phase B: thread=(w, slice) register accumulators;
// reduction by warp butterfly shuffles + tiny conflict-free SMEM pass.
// ---------------------------------------------------------------------------
__global__ void __launch_bounds__(128)
k_accum(const float* __restrict__ rs,
        const float* __restrict__ inta,
        const float* __restrict__ params,
        const float* __restrict__ cutoff,
        float*       __restrict__ swout)
{
    __shared__ float4 recs[CAP];
    __shared__ float2 dfc [CAP];
    __shared__ float  stab[96];      // [0:32) rs, [32:64) inta, [64:96) params
    __shared__ float  red [NL * NWAVE * 4];   // [l][w][warp]

    const int atom = blockIdx.x;
    const int t    = threadIdx.x;
    const int warp = t >> 5;
    const int lane = t & 31;

    if (t < 32) {
        stab[t]      = rs[t];
        stab[32 + t] = inta[t];
        stab[64 + t] = params[t];
    }

    int n = d_cursor[atom];
    if (n > CAP) n = CAP;

    const float4* src = &d_rec[(size_t)atom * CAP];
    for (int i = t; i < n; i += 128) recs[i] = src[i];
    __syncthreads();
    if (t == 0) d_cursor[atom] = 0;           // self-clean for next replay

    // Phase A: per-pair distance + cutoff
    const float icp = 3.14159265358979323846f / cutoff[0];
    for (int p = t; p < n; p += 128) {
        float4 v = recs[p];
        float d  = sqrtf(v.x*v.x + v.y*v.y + v.z*v.z);
        float c  = 0.5f * __cosf(d * icp) + 0.5f;
        dfc[p]   = make_float2(d, c * c);
    }
    __syncthreads();

    // Phase B: thread = (w = t&7, slice = t>>3)
    const int w  = t & 7;
    const int sl = t >> 3;

    float acc[NL];
#pragma unroll
    for (int l = 0; l < NL; ++l) acc[l] = 0.f;

    for (int p = sl; p < n; p += 16) {
        float4 v  = recs[p];
        float2 df = dfc[p];
        int   sp  = __float_as_int(v.w);
        float tt  = df.x - stab[sp*8 + w];
        float r   = stab[64 + sp*8 + w] * __expf(stab[32 + sp*8 + w] * tt * tt);
        float q   = df.y * r;
        float qx = q * v.x, qy = q * v.y, qz = q * v.z;
        acc[0]  += q;
        acc[1]  += qx;        acc[2]  += qy;        acc[3]  += qz;
        acc[4]  += qx * v.x;  acc[5]  += qx * v.y;  acc[6]  += qx * v.z;
        acc[7]  += qy * v.x;  acc[8]  += qy * v.y;  acc[9]  += qy * v.z;
        acc[10] += qz * v.x;  acc[11] += qz * v.y;  acc[12] += qz * v.z;
    }

    // warp reduction over slices (lanes w, w+8, w+16, w+24 share w)
#pragma unroll
    for (int l = 0; l < NL; ++l) {
        acc[l] += __shfl_xor_sync(0xffffffffu, acc[l], 8);
        acc[l] += __shfl_xor_sync(0xffffffffu, acc[l], 16);
    }
    if (lane < 8) {
#pragma unroll
        for (int l = 0; l < NL; ++l)
            red[(l * NWAVE + lane) * 4 + warp] = acc[l];
    }
    __syncthreads();

    if (t < NFEAT) {
        float4 v = *reinterpret_cast<const float4*>(&red[t * 4]);
        swout[(size_t)atom * NFEAT + t] = (v.x + v.y) + (v.z + v.w);
    }
}

// ---------------------------------------------------------------------------
// Kernel 2b: density[atom][m] = sum_l ( sum_w sw[l][w]*hp[l][w][m] )^2
// sw read as float4 (26 LDS.128/atom instead of 104 LDS.32).
// ---------------------------------------------------------------------------
__global__ void __launch_bounds__(128)
k_stage2(const float* __restrict__ hyper,      // (3, 8, 128)
         const int*   __restrict__ index_para, // (13,)
         const float* __restrict__ sw,         // (8192, 104)
         float*       __restrict__ out)        // (8192, 128)
{
    const int t = threadIdx.x;

    float hp[NFEAT];
#pragma unroll
    for (int l = 0; l < NL; ++l) {
        int ip = index_para[l];
#pragma unroll
        for (int w = 0; w < NWAVE; ++w)
            hp[l*NWAVE + w] = hyper[(ip*NWAVE + w)*NORBIT + t];
    }

    __shared__ float swsm[GATOMS * NFEAT];
    const int base = blockIdx.x * GATOMS;

    for (int i = t; i < GATOMS * NFEAT; i += 128)
        swsm[i] = sw[(size_t)base * NFEAT + i];
    __syncthreads();

#pragma unroll 2
    for (int g = 0; g < GATOMS; ++g) {
        const float4* s4 = reinterpret_cast<const float4*>(&swsm[g * NFEAT]);
        float dens = 0.f;
#pragma unroll
        for (int l = 0; l < NL; ++l) {
            float4 a = s4[l*2], b = s4[l*2+1];
            float h = a.x*hp[l*8+0] + a.y*hp[l*8+1] + a.z*hp[l*8+2] + a.w*hp[l*8+3]
                    + b.x*hp[l*8+4] + b.y*hp[l*8+5] + b.z*hp[l*8+6] + b.w*hp[l*8+7];
            dens += h * h;
        }
        out[(size_t)(base + g)*NORBIT + t] = dens;
    }
}

// ---------------------------------------------------------------------------
extern "C" void kernel_launch(void* const* d_in, const int* in_sizes, int n_in,
                              void* d_out, int out_size)
{
    const float* cart    = (const float*)d_in[0];
    const int*   species = (const int*)  d_in[2];
    const int*   aidx    = (const int*)  d_in[3];
    const float* shifts  = (const float*)d_in[4];
    const float* rs      = (const float*)d_in[5];
    const float* inta    = (const float*)d_in[6];
    const float* params  = (const float*)d_in[7];
    const float* hyper   = (const float*)d_in[8];
    const int*   ipara   = (const int*)  d_in[9];
    const float* cutoff  = (const float*)d_in[10];
    float*       out     = (float*)d_out;

    void* swp = nullptr;
    cudaGetSymbolAddress(&swp, d_sw);

    dim3 pgrid(NPAIR / 1024, NBATCH);
    k_pairs<<<pgrid, 256>>>(cart, species, aidx, shifts);
    k_accum<<<TOTATOM, 128>>>(rs, inta, params, cutoff, (float*)swp);
    k_stage2<<<TOTATOM / GATOMS, 128>>>(hyper, ipara, (const float*)swp, out);
}